// round 8
// baseline (speedup 1.0000x reference)
#include <cuda_runtime.h>

#define N_NODES 100000
#define N_EDGES 1600000
#define F 128
#define NGRAPH 64
#define FULLMASK 0xffffffffu

// ---------------- scratch (device globals; no allocations) ----------------
__device__ float g_dinv[N_NODES];
__device__ int   g_deg[N_NODES];
__device__ int   g_ptr[N_NODES + 1];
__device__ int   g_cursor[N_NODES];
__device__ int   g_bsum[128];
__device__ int2  g_csr[N_EDGES];          // {src, norm as float bits}
__device__ float g_xw [(size_t)N_NODES * F];
__device__ float g_h  [(size_t)N_NODES * F];
__device__ float g_pool[NGRAPH * F];

// ---------------- helpers ----------------
__device__ __forceinline__ void fma2(unsigned long long& c, unsigned long long a,
                                     unsigned long long b) {
    asm("fma.rn.f32x2 %0, %1, %2, %0;" : "+l"(c) : "l"(a), "l"(b));
}
__device__ __forceinline__ unsigned long long pack2(float a) {
    unsigned long long r;
    asm("mov.b64 %0, {%1, %1};" : "=l"(r) : "f"(a));
    return r;
}
__device__ __forceinline__ float2 unpack2(unsigned long long v) {
    float2 r;
    asm("mov.b64 {%0, %1}, %2;" : "=f"(r.x), "=f"(r.y) : "l"(v));
    return r;
}
__device__ __forceinline__ void facc(float4& a, float n, float4 v) {
    a.x = fmaf(n, v.x, a.x); a.y = fmaf(n, v.y, a.y);
    a.z = fmaf(n, v.z, a.z); a.w = fmaf(n, v.w, a.w);
}

// ---------------- small kernels ----------------
__global__ void k_zero_i(int* p, int n) {
    int i = blockIdx.x * blockDim.x + threadIdx.x;
    if (i < n) p[i] = 0;
}
__global__ void k_zero_f4(float4* p, int n4) {
    int i = blockIdx.x * blockDim.x + threadIdx.x;
    if (i < n4) p[i] = make_float4(0.f, 0.f, 0.f, 0.f);
}
__global__ void k_degree(const int* __restrict__ col) {
    int i = blockIdx.x * blockDim.x + threadIdx.x;
    int stride = gridDim.x * blockDim.x;
    for (; i < N_EDGES; i += stride) atomicAdd(&g_deg[col[i]], 1);
}
__global__ void k_dinv() {
    int i = blockIdx.x * blockDim.x + threadIdx.x;
    if (i < N_NODES) g_dinv[i] = rsqrtf((float)g_deg[i] + 2.0f);
}

// ---------------- prefix scan over deg -> ptr (and cursor) ----------------
__global__ void k_scan_local() {
    __shared__ int wsum[32];
    int tid = threadIdx.x, lane = tid & 31, wid = tid >> 5;
    int i = blockIdx.x * 1024 + tid;
    int v = (i < N_NODES) ? g_deg[i] : 0;
    int x = v;
    #pragma unroll
    for (int d = 1; d < 32; d <<= 1) {
        int y = __shfl_up_sync(FULLMASK, x, d);
        if (lane >= d) x += y;
    }
    if (lane == 31) wsum[wid] = x;
    __syncthreads();
    if (wid == 0) {
        int w = wsum[lane];
        int xx = w;
        #pragma unroll
        for (int d = 1; d < 32; d <<= 1) {
            int y = __shfl_up_sync(FULLMASK, xx, d);
            if (lane >= d) xx += y;
        }
        wsum[lane] = xx - w;
        if (lane == 31) g_bsum[blockIdx.x] = xx;
    }
    __syncthreads();
    if (i < N_NODES) g_ptr[i] = x - v + wsum[wid];
}
__global__ void k_scan_bsum(int nb) {
    __shared__ int s[128];
    int t = threadIdx.x;
    s[t] = (t < nb) ? g_bsum[t] : 0;
    __syncthreads();
    if (t == 0) {
        int acc = 0;
        for (int i = 0; i < nb; i++) { int v = s[i]; s[i] = acc; acc += v; }
    }
    __syncthreads();
    if (t < nb) g_bsum[t] = s[t];
}
__global__ void k_scan_add() {
    int i = blockIdx.x * 1024 + threadIdx.x;
    if (i < N_NODES) {
        int p = g_ptr[i] + g_bsum[blockIdx.x];
        g_ptr[i] = p;
        g_cursor[i] = p;
    }
    if (i == 0) g_ptr[N_NODES] = N_EDGES;
}

// ---------------- CSR fill: bucket edges by col ----------------
__global__ void k_fill(const int* __restrict__ row, const int* __restrict__ col) {
    int i = blockIdx.x * blockDim.x + threadIdx.x;
    if (i >= N_EDGES) return;
    int r = row[i];
    int c = col[i];
    float nrm = g_dinv[r] * g_dinv[c];
    int pos = atomicAdd(&g_cursor[c], 1);
    g_csr[pos] = make_int2(r, __float_as_int(nrm));
}

// ---------------- GEMM: C[M,128] = A[M,128] @ W[128,128] (fp32, f32x2) --------
#define GEMM_SMEM ((64 * 129 + 128 * 128) * 4)
__global__ void k_gemm(const float* __restrict__ A, const float* __restrict__ W,
                       float* __restrict__ C, int M) {
    extern __shared__ float sm[];
    float* As = sm;               // 64 x 129 (padded)
    float* Ws = sm + 64 * 129;    // 128 x 128
    const int t  = threadIdx.x;   // 256 threads
    const int m0 = blockIdx.x * 64;

    #pragma unroll 4
    for (int i = t; i < 128 * 32; i += 256)
        ((float4*)Ws)[i] = ((const float4*)W)[i];

    for (int i = t; i < 64 * 32; i += 256) {
        int r = i >> 5, c = i & 31;
        float4 v = make_float4(0.f, 0.f, 0.f, 0.f);
        if (m0 + r < M) v = ((const float4*)(A + (size_t)(m0 + r) * F))[c];
        float* p = As + r * 129 + c * 4;
        p[0] = v.x; p[1] = v.y; p[2] = v.z; p[3] = v.w;
    }
    __syncthreads();

    const int tx = t & 15;
    const int ty = t >> 4;

    unsigned long long acc[4][4];
    #pragma unroll
    for (int i = 0; i < 4; i++)
        #pragma unroll
        for (int j = 0; j < 4; j++) acc[i][j] = 0ULL;

    const float* a_base = As + (ty * 4) * 129;
    const float* b_base = Ws + tx * 8;

    #pragma unroll 4
    for (int k = 0; k < 128; k++) {
        unsigned long long pa0 = pack2(a_base[k]);
        unsigned long long pa1 = pack2(a_base[129 + k]);
        unsigned long long pa2 = pack2(a_base[2 * 129 + k]);
        unsigned long long pa3 = pack2(a_base[3 * 129 + k]);
        const ulonglong2* bp = (const ulonglong2*)(b_base + k * 128);
        ulonglong2 b01 = bp[0];
        ulonglong2 b23 = bp[1];
        fma2(acc[0][0], pa0, b01.x); fma2(acc[0][1], pa0, b01.y);
        fma2(acc[0][2], pa0, b23.x); fma2(acc[0][3], pa0, b23.y);
        fma2(acc[1][0], pa1, b01.x); fma2(acc[1][1], pa1, b01.y);
        fma2(acc[1][2], pa1, b23.x); fma2(acc[1][3], pa1, b23.y);
        fma2(acc[2][0], pa2, b01.x); fma2(acc[2][1], pa2, b01.y);
        fma2(acc[2][2], pa2, b23.x); fma2(acc[2][3], pa2, b23.y);
        fma2(acc[3][0], pa3, b01.x); fma2(acc[3][1], pa3, b01.y);
        fma2(acc[3][2], pa3, b23.x); fma2(acc[3][3], pa3, b23.y);
    }

    #pragma unroll
    for (int i = 0; i < 4; i++) {
        int r = m0 + ty * 4 + i;
        if (r < M) {
            float2 v0 = unpack2(acc[i][0]);
            float2 v1 = unpack2(acc[i][1]);
            float2 v2 = unpack2(acc[i][2]);
            float2 v3 = unpack2(acc[i][3]);
            float4* dst = (float4*)(C + (size_t)r * F + tx * 8);
            dst[0] = make_float4(v0.x, v0.y, v1.x, v1.y);
            dst[1] = make_float4(v2.x, v2.y, v3.x, v3.y);
        }
    }
}

// ---------------- CSR gather aggregation: warp per node, NO shfl ------------
// All lanes read the same g_csr[e] (uniform address -> HW broadcast).
// 8 gathers kept in flight for MLP. acc = 2*dinv^2*xw[n] + sum nrm*xw[src];
// +bias; relu. LAYER2: dropout (*mask*2) + fused segment-max pool via atomicMax.
template<bool LAYER2>
__global__ void k_gather(const float4* __restrict__ xw4, const float* __restrict__ bias,
                         float4* __restrict__ out, const int4* __restrict__ mask4,
                         const int* __restrict__ batch) {
    int n = (blockIdx.x * blockDim.x + threadIdx.x) >> 5;
    if (n >= N_NODES) return;
    const int lane = threadIdx.x & 31;
    const int beg = __ldg(&g_ptr[n]);
    const int end = __ldg(&g_ptr[n + 1]);
    const float dc = __ldg(&g_dinv[n]);

    float4 self = __ldg(&xw4[(size_t)n * 32 + lane]);
    float s2 = 2.f * dc * dc;
    float4 acc = make_float4(s2 * self.x, s2 * self.y, s2 * self.z, s2 * self.w);

    int e = beg;
    for (; e + 8 <= end; e += 8) {
        int2 p0 = __ldg(&g_csr[e]);
        int2 p1 = __ldg(&g_csr[e + 1]);
        int2 p2 = __ldg(&g_csr[e + 2]);
        int2 p3 = __ldg(&g_csr[e + 3]);
        int2 p4 = __ldg(&g_csr[e + 4]);
        int2 p5 = __ldg(&g_csr[e + 5]);
        int2 p6 = __ldg(&g_csr[e + 6]);
        int2 p7 = __ldg(&g_csr[e + 7]);
        float4 v0 = __ldg(&xw4[(size_t)p0.x * 32 + lane]);
        float4 v1 = __ldg(&xw4[(size_t)p1.x * 32 + lane]);
        float4 v2 = __ldg(&xw4[(size_t)p2.x * 32 + lane]);
        float4 v3 = __ldg(&xw4[(size_t)p3.x * 32 + lane]);
        float4 v4 = __ldg(&xw4[(size_t)p4.x * 32 + lane]);
        float4 v5 = __ldg(&xw4[(size_t)p5.x * 32 + lane]);
        float4 v6 = __ldg(&xw4[(size_t)p6.x * 32 + lane]);
        float4 v7 = __ldg(&xw4[(size_t)p7.x * 32 + lane]);
        facc(acc, __int_as_float(p0.y), v0);
        facc(acc, __int_as_float(p1.y), v1);
        facc(acc, __int_as_float(p2.y), v2);
        facc(acc, __int_as_float(p3.y), v3);
        facc(acc, __int_as_float(p4.y), v4);
        facc(acc, __int_as_float(p5.y), v5);
        facc(acc, __int_as_float(p6.y), v6);
        facc(acc, __int_as_float(p7.y), v7);
    }
    for (; e < end; e++) {
        int2 p = __ldg(&g_csr[e]);
        float4 v = __ldg(&xw4[(size_t)p.x * 32 + lane]);
        facc(acc, __int_as_float(p.y), v);
    }

    float4 bv = ((const float4*)bias)[lane];
    acc.x = fmaxf(acc.x + bv.x, 0.f);
    acc.y = fmaxf(acc.y + bv.y, 0.f);
    acc.z = fmaxf(acc.z + bv.z, 0.f);
    acc.w = fmaxf(acc.w + bv.w, 0.f);

    if (!LAYER2) {
        out[(size_t)n * 32 + lane] = acc;
    } else {
        int4 m = __ldg(&mask4[(size_t)n * 32 + lane]);
        acc.x *= (float)(m.x << 1);
        acc.y *= (float)(m.y << 1);
        acc.z *= (float)(m.z << 1);
        acc.w *= (float)(m.w << 1);
        int* pp = (int*)(g_pool + __ldg(&batch[n]) * F + lane * 4);
        atomicMax(pp + 0, __float_as_int(acc.x));
        atomicMax(pp + 1, __float_as_int(acc.y));
        atomicMax(pp + 2, __float_as_int(acc.z));
        atomicMax(pp + 3, __float_as_int(acc.w));
    }
}

// ---------------- head: relu(pool @ Wm + bm) @ Wf + bf -> out[64,32] ----------
__global__ void k_head(const float* __restrict__ Wm, const float* __restrict__ bm,
                       const float* __restrict__ Wf, const float* __restrict__ bf,
                       float* __restrict__ out) {
    __shared__ float sh[NGRAPH * F];
    int t = threadIdx.x;               // 256
    for (int i = t; i < NGRAPH * F; i += 256) {
        int g = i >> 7, f = i & 127;
        float acc = bm[f];
        const float* pg = g_pool + g * F;
        #pragma unroll 8
        for (int k = 0; k < 128; k++) acc = fmaf(pg[k], Wm[k * F + f], acc);
        sh[i] = fmaxf(acc, 0.f);
    }
    __syncthreads();
    for (int i = t; i < NGRAPH * 32; i += 256) {
        int g = i >> 5, o = i & 31;
        float acc = bf[o];
        const float* hg = sh + g * F;
        #pragma unroll 8
        for (int k = 0; k < 128; k++) acc = fmaf(hg[k], Wf[k * 32 + o], acc);
        out[i] = acc;
    }
}

// ---------------- launch ----------------
extern "C" void kernel_launch(void* const* d_in, const int* in_sizes, int n_in,
                              void* d_out, int out_size) {
    const float* x     = (const float*)d_in[0];
    const int*   ei    = (const int*)d_in[1];
    const int*   batch = (const int*)d_in[2];
    const int*   mask  = (const int*)d_in[3];
    const float* W1    = (const float*)d_in[4];
    const float* b1    = (const float*)d_in[5];
    const float* W2    = (const float*)d_in[6];
    const float* b2    = (const float*)d_in[7];
    const float* Wm    = (const float*)d_in[8];
    const float* bm    = (const float*)d_in[9];
    const float* Wf    = (const float*)d_in[10];
    const float* bf    = (const float*)d_in[11];
    float* out = (float*)d_out;
    (void)in_sizes; (void)n_in; (void)out_size;

    float *xw, *h, *pool;
    int* deg;
    cudaGetSymbolAddress((void**)&xw,   g_xw);
    cudaGetSymbolAddress((void**)&h,    g_h);
    cudaGetSymbolAddress((void**)&pool, g_pool);
    cudaGetSymbolAddress((void**)&deg,  g_deg);

    cudaFuncSetAttribute(k_gemm, cudaFuncAttributeMaxDynamicSharedMemorySize, GEMM_SMEM);

    const int* row = ei;
    const int* col = ei + N_EDGES;

    const int NB = 98;                                   // ceil(100000/1024)
    const int gemm_blocks   = 1563;                      // ceil(100000/64)
    const int gather_blocks = 12500;                     // warp/node, 8 warps/blk
    const int fill_blocks   = 6250;                      // ceil(1600000/256)

    // ---- setup: degrees, dinv, CSR ----
    k_zero_i<<<391, 256>>>(deg, N_NODES);
    k_zero_f4<<<8, 256>>>((float4*)pool, NGRAPH * F / 4);
    k_degree<<<1184, 256>>>(col);
    k_dinv<<<391, 256>>>();
    k_scan_local<<<NB, 1024>>>();
    k_scan_bsum<<<1, 128>>>(NB);
    k_scan_add<<<NB, 1024>>>();
    k_fill<<<fill_blocks, 256>>>(row, col);

    // ---- layer 1: xw = x@W1; h = relu(agg(xw) + b1) ----
    k_gemm<<<gemm_blocks, 256, GEMM_SMEM>>>(x, W1, xw, N_NODES);
    k_gather<false><<<gather_blocks, 256>>>((const float4*)xw, b1, (float4*)h,
                                            nullptr, nullptr);

    // ---- layer 2: xw = h@W2; fused agg + b2 + relu + dropout + max-pool ----
    k_gemm<<<gemm_blocks, 256, GEMM_SMEM>>>(h, W2, xw, N_NODES);
    k_gather<true><<<gather_blocks, 256>>>((const float4*)xw, b2, nullptr,
                                           (const int4*)mask, batch);

    // ---- MLP head ----
    k_head<<<1, 256>>>(Wm, bm, Wf, bf, out);
}

// round 10
// speedup vs baseline: 1.4454x; 1.4454x over previous
#include <cuda_runtime.h>
#include <cuda_fp16.h>

#define N_NODES 100000
#define N_EDGES 1600000
#define F 128
#define NGRAPH 64

// ---------------- scratch (device globals; no allocations) ----------------
__device__ float  g_dinv[N_NODES];
__device__ int    g_deg[N_NODES];
__device__ __half g_xwh[(size_t)N_NODES * F];   // dinv[row] * xw, fp16
__device__ float  g_agg[(size_t)N_NODES * F];
__device__ float  g_pool[NGRAPH * F];

// ---------------- helpers ----------------
__device__ __forceinline__ void fma2(unsigned long long& c, unsigned long long a,
                                     unsigned long long b) {
    asm("fma.rn.f32x2 %0, %1, %2, %0;" : "+l"(c) : "l"(a), "l"(b));
}
__device__ __forceinline__ unsigned long long pack2(float a) {
    unsigned long long r;
    asm("mov.b64 %0, {%1, %1};" : "=l"(r) : "f"(a));
    return r;
}
__device__ __forceinline__ float2 unpack2(unsigned long long v) {
    float2 r;
    asm("mov.b64 {%0, %1}, %2;" : "=f"(r.x), "=f"(r.y) : "l"(v));
    return r;
}
// bit-cast __half2 -> unsigned (proper, no UB puns)
__device__ __forceinline__ unsigned h2u(__half2 h) {
    union { __half2 h; unsigned u; } cvt;
    cvt.h = h;
    return cvt.u;
}
__device__ __forceinline__ __half2 u2h(unsigned u) {
    union { unsigned u; __half2 h; } cvt;
    cvt.u = u;
    return cvt.h;
}

// ---------------- small kernels ----------------
__global__ void k_zero_i(int* p, int n) {
    int i = blockIdx.x * blockDim.x + threadIdx.x;
    if (i < n) p[i] = 0;
}
__global__ void k_zero_f4(float4* p, int n4) {
    int i = blockIdx.x * blockDim.x + threadIdx.x;
    if (i < n4) p[i] = make_float4(0.f, 0.f, 0.f, 0.f);
}
__global__ void k_degree(const int* __restrict__ col) {
    int i = blockIdx.x * blockDim.x + threadIdx.x;
    int stride = gridDim.x * blockDim.x;
    for (; i < N_EDGES; i += stride) atomicAdd(&g_deg[col[i]], 1);
}
__global__ void k_dinv() {
    int i = blockIdx.x * blockDim.x + threadIdx.x;
    if (i < N_NODES) g_dinv[i] = rsqrtf((float)g_deg[i] + 2.0f);
}

// ---- GEMM + fused epilogue:
//   t   = (RELU_A ? relu(A) : A) @ W                  (f32, in regs)
//   xwh = dinv[r] * t         (fp16, message source for edge scatter)
//   agg = 2*dinv^2 * t + bias (f32, self-loop term pre-seeds the scatter)
#define GEMM_SMEM ((64 * 129 + 128 * 128) * 4)
template<bool RELU_A>
__global__ void k_gemm_init(const float* __restrict__ A, const float* __restrict__ W,
                            const float* __restrict__ bias,
                            __half* __restrict__ xwh, float* __restrict__ agg, int M) {
    extern __shared__ float sm[];
    float* As = sm;               // 64 x 129 (padded)
    float* Ws = sm + 64 * 129;    // 128 x 128
    const int t  = threadIdx.x;   // 256 threads
    const int m0 = blockIdx.x * 64;

    #pragma unroll 4
    for (int i = t; i < 128 * 32; i += 256)
        ((float4*)Ws)[i] = ((const float4*)W)[i];

    for (int i = t; i < 64 * 32; i += 256) {
        int r = i >> 5, c = i & 31;
        float4 v = make_float4(0.f, 0.f, 0.f, 0.f);
        if (m0 + r < M) v = ((const float4*)(A + (size_t)(m0 + r) * F))[c];
        if (RELU_A) {
            v.x = fmaxf(v.x, 0.f); v.y = fmaxf(v.y, 0.f);
            v.z = fmaxf(v.z, 0.f); v.w = fmaxf(v.w, 0.f);
        }
        float* p = As + r * 129 + c * 4;
        p[0] = v.x; p[1] = v.y; p[2] = v.z; p[3] = v.w;
    }
    __syncthreads();

    const int tx = t & 15;   // cols tx*8 .. tx*8+7
    const int ty = t >> 4;   // rows ty*4 .. ty*4+3

    unsigned long long acc[4][4];
    #pragma unroll
    for (int i = 0; i < 4; i++)
        #pragma unroll
        for (int j = 0; j < 4; j++) acc[i][j] = 0ULL;

    const float* a_base = As + (ty * 4) * 129;
    const float* b_base = Ws + tx * 8;

    #pragma unroll 4
    for (int k = 0; k < 128; k++) {
        unsigned long long pa0 = pack2(a_base[k]);
        unsigned long long pa1 = pack2(a_base[129 + k]);
        unsigned long long pa2 = pack2(a_base[2 * 129 + k]);
        unsigned long long pa3 = pack2(a_base[3 * 129 + k]);
        const ulonglong2* bp = (const ulonglong2*)(b_base + k * 128);
        ulonglong2 b01 = bp[0];
        ulonglong2 b23 = bp[1];
        fma2(acc[0][0], pa0, b01.x); fma2(acc[0][1], pa0, b01.y);
        fma2(acc[0][2], pa0, b23.x); fma2(acc[0][3], pa0, b23.y);
        fma2(acc[1][0], pa1, b01.x); fma2(acc[1][1], pa1, b01.y);
        fma2(acc[1][2], pa1, b23.x); fma2(acc[1][3], pa1, b23.y);
        fma2(acc[2][0], pa2, b01.x); fma2(acc[2][1], pa2, b01.y);
        fma2(acc[2][2], pa2, b23.x); fma2(acc[2][3], pa2, b23.y);
        fma2(acc[3][0], pa3, b01.x); fma2(acc[3][1], pa3, b01.y);
        fma2(acc[3][2], pa3, b23.x); fma2(acc[3][3], pa3, b23.y);
    }

    float4 bv0 = ((const float4*)bias)[tx * 2];
    float4 bv1 = ((const float4*)bias)[tx * 2 + 1];

    #pragma unroll
    for (int i = 0; i < 4; i++) {
        int r = m0 + ty * 4 + i;
        if (r < M) {
            float2 v0 = unpack2(acc[i][0]);
            float2 v1 = unpack2(acc[i][1]);
            float2 v2 = unpack2(acc[i][2]);
            float2 v3 = unpack2(acc[i][3]);
            float4 o0 = make_float4(v0.x, v0.y, v1.x, v1.y);
            float4 o1 = make_float4(v2.x, v2.y, v3.x, v3.y);

            float d = g_dinv[r];
            // fp16 message source: dinv[r] * xw  (8 halves = one 16B store)
            uint4 hp;
            hp.x = h2u(__floats2half2_rn(d * o0.x, d * o0.y));
            hp.y = h2u(__floats2half2_rn(d * o0.z, d * o0.w));
            hp.z = h2u(__floats2half2_rn(d * o1.x, d * o1.y));
            hp.w = h2u(__floats2half2_rn(d * o1.z, d * o1.w));
            *((uint4*)(xwh + (size_t)r * F + tx * 8)) = hp;

            // f32 agg seed: 2*dinv^2*xw + bias
            float s = 2.f * d * d;
            float4 a0, a1;
            a0.x = fmaf(s, o0.x, bv0.x); a0.y = fmaf(s, o0.y, bv0.y);
            a0.z = fmaf(s, o0.z, bv0.z); a0.w = fmaf(s, o0.w, bv0.w);
            a1.x = fmaf(s, o1.x, bv1.x); a1.y = fmaf(s, o1.y, bv1.y);
            a1.z = fmaf(s, o1.z, bv1.z); a1.w = fmaf(s, o1.w, bv1.w);
            float4* adst = (float4*)(agg + (size_t)r * F + tx * 8);
            adst[0] = a0;
            adst[1] = a1;
        }
    }
}

// ---------------- edge scatter: agg[col] += dinv[col] * xwh[row] ----------
// xwh already carries dinv[row]. Warp handles 4 edges one-shot; lane owns 4
// features read as 8B fp16, converted to f32, scattered via red.v4 atomics.
__global__ void k_edge(const int* __restrict__ row, const int* __restrict__ col,
                       const __half* __restrict__ src, float* __restrict__ dst) {
    int warp = (blockIdx.x * blockDim.x + threadIdx.x) >> 5;
    int lane = threadIdx.x & 31;
    int e = warp * 4;
    if (e >= N_EDGES) return;   // N_EDGES % 4 == 0

    int r0 = __ldg(row + e),     c0 = __ldg(col + e);
    int r1 = __ldg(row + e + 1), c1 = __ldg(col + e + 1);
    int r2 = __ldg(row + e + 2), c2 = __ldg(col + e + 2);
    int r3 = __ldg(row + e + 3), c3 = __ldg(col + e + 3);

    uint2 w0 = __ldg((const uint2*)(src + ((size_t)r0 << 7)) + lane);
    uint2 w1 = __ldg((const uint2*)(src + ((size_t)r1 << 7)) + lane);
    uint2 w2 = __ldg((const uint2*)(src + ((size_t)r2 << 7)) + lane);
    uint2 w3 = __ldg((const uint2*)(src + ((size_t)r3 << 7)) + lane);

    float n0 = __ldg(&g_dinv[c0]);
    float n1 = __ldg(&g_dinv[c1]);
    float n2 = __ldg(&g_dinv[c2]);
    float n3 = __ldg(&g_dinv[c3]);

    float2 f0a = __half22float2(u2h(w0.x)), f0b = __half22float2(u2h(w0.y));
    float2 f1a = __half22float2(u2h(w1.x)), f1b = __half22float2(u2h(w1.y));
    float2 f2a = __half22float2(u2h(w2.x)), f2b = __half22float2(u2h(w2.y));
    float2 f3a = __half22float2(u2h(w3.x)), f3b = __half22float2(u2h(w3.y));

    float* a0 = dst + ((size_t)c0 << 7) + lane * 4;
    float* a1 = dst + ((size_t)c1 << 7) + lane * 4;
    float* a2 = dst + ((size_t)c2 << 7) + lane * 4;
    float* a3 = dst + ((size_t)c3 << 7) + lane * 4;

    asm volatile("red.global.add.v4.f32 [%0], {%1, %2, %3, %4};"
                 :: "l"(a0), "f"(n0 * f0a.x), "f"(n0 * f0a.y),
                    "f"(n0 * f0b.x), "f"(n0 * f0b.y) : "memory");
    asm volatile("red.global.add.v4.f32 [%0], {%1, %2, %3, %4};"
                 :: "l"(a1), "f"(n1 * f1a.x), "f"(n1 * f1a.y),
                    "f"(n1 * f1b.x), "f"(n1 * f1b.y) : "memory");
    asm volatile("red.global.add.v4.f32 [%0], {%1, %2, %3, %4};"
                 :: "l"(a2), "f"(n2 * f2a.x), "f"(n2 * f2a.y),
                    "f"(n2 * f2b.x), "f"(n2 * f2b.y) : "memory");
    asm volatile("red.global.add.v4.f32 [%0], {%1, %2, %3, %4};"
                 :: "l"(a3), "f"(n3 * f3a.x), "f"(n3 * f3a.y),
                    "f"(n3 * f3b.x), "f"(n3 * f3b.y) : "memory");
}

// ---------------- relu + dropout + segment-max pool (reads agg) -------------
__global__ void k_pool(const float* __restrict__ agg, const int* __restrict__ mask,
                       const int* __restrict__ batch) {
    int t  = threadIdx.x;           // feature
    int n0 = blockIdx.x * 64;
    int cur = -1;
    float mx = 0.f;
    for (int i = 0; i < 64; i++) {
        int n = n0 + i;
        if (n >= N_NODES) break;
        int bid = batch[n];
        if (bid != cur) {
            if (cur >= 0) atomicMax((int*)&g_pool[cur * F + t], __float_as_int(mx));
            cur = bid;
            mx = 0.f;
        }
        size_t idx = (size_t)n * F + t;
        float v = fmaxf(agg[idx], 0.f);
        v *= (float)(mask[idx] << 1);   // dropout: *mask*2
        mx = fmaxf(mx, v);
    }
    if (cur >= 0) atomicMax((int*)&g_pool[cur * F + t], __float_as_int(mx));
}

// ---------------- head: relu(pool @ Wm + bm) @ Wf + bf -> out[64,32] ----------
__global__ void k_head(const float* __restrict__ Wm, const float* __restrict__ bm,
                       const float* __restrict__ Wf, const float* __restrict__ bf,
                       float* __restrict__ out) {
    __shared__ float sh[NGRAPH * F];
    int t = threadIdx.x;               // 256
    for (int i = t; i < NGRAPH * F; i += 256) {
        int g = i >> 7, f = i & 127;
        float acc = bm[f];
        const float* pg = g_pool + g * F;
        #pragma unroll 8
        for (int k = 0; k < 128; k++) acc = fmaf(pg[k], Wm[k * F + f], acc);
        sh[i] = fmaxf(acc, 0.f);
    }
    __syncthreads();
    for (int i = t; i < NGRAPH * 32; i += 256) {
        int g = i >> 5, o = i & 31;
        float acc = bf[o];
        const float* hg = sh + g * F;
        #pragma unroll 8
        for (int k = 0; k < 128; k++) acc = fmaf(hg[k], Wf[k * 32 + o], acc);
        out[i] = acc;
    }
}

// ---------------- launch ----------------
extern "C" void kernel_launch(void* const* d_in, const int* in_sizes, int n_in,
                              void* d_out, int out_size) {
    const float* x     = (const float*)d_in[0];
    const int*   ei    = (const int*)d_in[1];
    const int*   batch = (const int*)d_in[2];
    const int*   mask  = (const int*)d_in[3];
    const float* W1    = (const float*)d_in[4];
    const float* b1    = (const float*)d_in[5];
    const float* W2    = (const float*)d_in[6];
    const float* b2    = (const float*)d_in[7];
    const float* Wm    = (const float*)d_in[8];
    const float* bm    = (const float*)d_in[9];
    const float* Wf    = (const float*)d_in[10];
    const float* bf    = (const float*)d_in[11];
    float* out = (float*)d_out;
    (void)in_sizes; (void)n_in; (void)out_size;

    __half* xwh;
    float *agg, *pool;
    int* deg;
    cudaGetSymbolAddress((void**)&xwh,  g_xwh);
    cudaGetSymbolAddress((void**)&agg,  g_agg);
    cudaGetSymbolAddress((void**)&pool, g_pool);
    cudaGetSymbolAddress((void**)&deg,  g_deg);

    cudaFuncSetAttribute(k_gemm_init<false>, cudaFuncAttributeMaxDynamicSharedMemorySize, GEMM_SMEM);
    cudaFuncSetAttribute(k_gemm_init<true>,  cudaFuncAttributeMaxDynamicSharedMemorySize, GEMM_SMEM);

    const int* row = ei;
    const int* col = ei + N_EDGES;

    const int gemm_blocks = 1563;                 // ceil(100000/64)
    const int pool_blocks = 1563;                 // ceil(100000/64)
    const int edge_blocks = 50000;                // 1 warp = 4 edges, 8 warps/blk

    // ---- setup ----
    k_zero_i<<<391, 256>>>(deg, N_NODES);
    k_zero_f4<<<8, 256>>>((float4*)pool, NGRAPH * F / 4);
    k_degree<<<1184, 256>>>(col);
    k_dinv<<<391, 256>>>();

    // ---- layer 1 ----
    k_gemm_init<false><<<gemm_blocks, 256, GEMM_SMEM>>>(x, W1, b1, xwh, agg, N_NODES);
    k_edge<<<edge_blocks, 256>>>(row, col, xwh, agg);

    // ---- layer 2 (relu of layer-1 agg fused into GEMM A load) ----
    k_gemm_init<true><<<gemm_blocks, 256, GEMM_SMEM>>>(agg, W2, b2, xwh, agg, N_NODES);
    k_edge<<<edge_blocks, 256>>>(row, col, xwh, agg);

    // ---- relu + dropout + max-pool ----
    k_pool<<<pool_blocks, 128>>>(agg, mask, batch);

    // ---- MLP head ----
    k_head<<<1, 256>>>(Wm, bm, Wf, bf, out);
}

// round 13
// speedup vs baseline: 1.9939x; 1.3795x over previous
#include <cuda_runtime.h>
#include <cuda_fp16.h>

#define N_NODES 100000
#define N_EDGES 1600000
#define F 128
#define NGRAPH 64

// ---------------- scratch (device globals; no allocations) ----------------
__device__ float  g_dinv[N_NODES];
__device__ int    g_deg[N_NODES];
__device__ __half g_xwh[(size_t)N_NODES * F];   // dinv[row] * xw, fp16
__device__ float  g_agg[(size_t)N_NODES * F];
__device__ float  g_pool[NGRAPH * F];

// ---------------- helpers ----------------
__device__ __forceinline__ unsigned h2u(__half2 h) {
    union { __half2 h; unsigned u; } cvt; cvt.h = h; return cvt.u;
}
__device__ __forceinline__ __half2 u2h(unsigned u) {
    union { unsigned u; __half2 h; } cvt; cvt.u = u; return cvt.h;
}
__device__ __forceinline__ unsigned smem_u32(const void* p) {
    return (unsigned)__cvta_generic_to_shared(p);
}

#define LDSM_X4(r0, r1, r2, r3, addr) \
    asm volatile("ldmatrix.sync.aligned.m8n8.x4.shared.b16 {%0,%1,%2,%3},[%4];" \
                 : "=r"(r0), "=r"(r1), "=r"(r2), "=r"(r3) : "r"(addr))
#define LDSM_X4_T(r0, r1, r2, r3, addr) \
    asm volatile("ldmatrix.sync.aligned.m8n8.x4.trans.shared.b16 {%0,%1,%2,%3},[%4];" \
                 : "=r"(r0), "=r"(r1), "=r"(r2), "=r"(r3) : "r"(addr))
#define MMA16816(c, a0, a1, a2, a3, b0, b1) \
    asm volatile("mma.sync.aligned.m16n8k16.row.col.f32.f16.f16.f32 " \
                 "{%0,%1,%2,%3},{%4,%5,%6,%7},{%8,%9},{%0,%1,%2,%3};" \
                 : "+f"(c[0]), "+f"(c[1]), "+f"(c[2]), "+f"(c[3]) \
                 : "r"(a0), "r"(a1), "r"(a2), "r"(a3), "r"(b0), "r"(b1))

// ---------------- small kernels ----------------
__global__ void k_zero_i(int* p, int n) {
    int i = blockIdx.x * blockDim.x + threadIdx.x;
    if (i < n) p[i] = 0;
}
__global__ void k_zero_f4(float4* p, int n4) {
    int i = blockIdx.x * blockDim.x + threadIdx.x;
    if (i < n4) p[i] = make_float4(0.f, 0.f, 0.f, 0.f);
}
__global__ void k_degree(const int* __restrict__ col) {
    int i = blockIdx.x * blockDim.x + threadIdx.x;
    int stride = gridDim.x * blockDim.x;
    for (; i < N_EDGES; i += stride) atomicAdd(&g_deg[col[i]], 1);
}
__global__ void k_dinv() {
    int i = blockIdx.x * blockDim.x + threadIdx.x;
    if (i < N_NODES) g_dinv[i] = rsqrtf((float)g_deg[i] + 2.0f);
}

// ---- Tensor-core GEMM + fused epilogue (HMMA m16n8k16, fp32 accum):
//   t   = (RELU_A ? relu(A) : A) @ W                  (fp16 inputs, f32 accum)
//   xwh = dinv[r] * t         (fp16, message source for edge scatter)
//   agg = 2*dinv^2 * t + bias (f32, self-loop term pre-seeds the scatter)
// Block: 64 rows x 128 cols, 256 threads = 8 warps (4 in M x 2 in N).
// smem: A 64x136 fp16, W 128x136 fp16 (stride 136 halves = 17*16B).
#define APITCH 136
#define GEMM_SMEM ((64 * APITCH + 128 * APITCH) * 2)
template<bool RELU_A>
__global__ void k_gemm_init(const float* __restrict__ A, const float* __restrict__ W,
                            const float* __restrict__ bias,
                            __half* __restrict__ xwh, float* __restrict__ agg, int M) {
    extern __shared__ __half sm[];
    __half* As = sm;                 // 64 x 136
    __half* Ws = sm + 64 * APITCH;   // 128 x 136
    const int t  = threadIdx.x;      // 256 threads
    const int m0 = blockIdx.x * 64;

    // load W (128x128 f32) -> fp16 smem  (Ws[k][n])
    #pragma unroll 4
    for (int i = t; i < 128 * 32; i += 256) {
        int r = i >> 5, c = i & 31;
        float4 v = ((const float4*)W)[i];
        uint2 hp;
        hp.x = h2u(__floats2half2_rn(v.x, v.y));
        hp.y = h2u(__floats2half2_rn(v.z, v.w));
        *((uint2*)(Ws + r * APITCH + c * 4)) = hp;
    }
    // load A tile (64x128 f32) -> fp16 smem (optional relu fused)
    for (int i = t; i < 64 * 32; i += 256) {
        int r = i >> 5, c = i & 31;
        float4 v = make_float4(0.f, 0.f, 0.f, 0.f);
        if (m0 + r < M) v = ((const float4*)(A + (size_t)(m0 + r) * F))[c];
        if (RELU_A) {
            v.x = fmaxf(v.x, 0.f); v.y = fmaxf(v.y, 0.f);
            v.z = fmaxf(v.z, 0.f); v.w = fmaxf(v.w, 0.f);
        }
        uint2 hp;
        hp.x = h2u(__floats2half2_rn(v.x, v.y));
        hp.y = h2u(__floats2half2_rn(v.z, v.w));
        *((uint2*)(As + r * APITCH + c * 4)) = hp;
    }
    __syncthreads();

    const int lane = t & 31;
    const int wid  = t >> 5;
    const int wm   = wid & 3;    // warp row block: 16 rows
    const int wn   = wid >> 2;   // warp col block: 64 cols

    float c[8][4];
    #pragma unroll
    for (int i = 0; i < 8; i++)
        #pragma unroll
        for (int j = 0; j < 4; j++) c[i][j] = 0.f;

    const int lr = lane & 15;    // ldmatrix row selector
    const int lc = lane >> 4;    // ldmatrix half selector

    #pragma unroll
    for (int k0 = 0; k0 < 8; k0++) {
        unsigned a0, a1, a2, a3;
        unsigned aaddr = smem_u32(As + (wm * 16 + lr) * APITCH + k0 * 16 + lc * 8);
        LDSM_X4(a0, a1, a2, a3, aaddr);
        #pragma unroll
        for (int tp = 0; tp < 4; tp++) {
            unsigned b0, b1, b2, b3;
            unsigned baddr = smem_u32(Ws + (k0 * 16 + lr) * APITCH
                                      + wn * 64 + tp * 16 + lc * 8);
            LDSM_X4_T(b0, b1, b2, b3, baddr);
            MMA16816(c[2 * tp],     a0, a1, a2, a3, b0, b1);
            MMA16816(c[2 * tp + 1], a0, a1, a2, a3, b2, b3);
        }
    }

    // epilogue: thread owns rows r1,r2 and col pairs (nb, nb+1) in 8 n-tiles
    const int r1 = m0 + wm * 16 + (lane >> 2);
    const int r2 = r1 + 8;
    float d1 = 0.f, d2 = 0.f;
    if (r1 < M) d1 = g_dinv[r1];
    if (r2 < M) d2 = g_dinv[r2];
    const float s1 = 2.f * d1 * d1;
    const float s2 = 2.f * d2 * d2;

    #pragma unroll
    for (int t8 = 0; t8 < 8; t8++) {
        int nb = wn * 64 + t8 * 8 + 2 * (lane & 3);
        float2 bv = ((const float2*)bias)[nb >> 1];
        if (r1 < M) {
            *((unsigned*)(xwh + (size_t)r1 * F + nb)) =
                h2u(__floats2half2_rn(d1 * c[t8][0], d1 * c[t8][1]));
            float2 av;
            av.x = fmaf(s1, c[t8][0], bv.x);
            av.y = fmaf(s1, c[t8][1], bv.y);
            *((float2*)(agg + (size_t)r1 * F + nb)) = av;
        }
        if (r2 < M) {
            *((unsigned*)(xwh + (size_t)r2 * F + nb)) =
                h2u(__floats2half2_rn(d2 * c[t8][2], d2 * c[t8][3]));
            float2 av;
            av.x = fmaf(s2, c[t8][2], bv.x);
            av.y = fmaf(s2, c[t8][3], bv.y);
            *((float2*)(agg + (size_t)r2 * F + nb)) = av;
        }
    }
}

// ---------------- edge scatter: agg[col] += dinv[col] * xwh[row] ----------
__global__ void k_edge(const int* __restrict__ row, const int* __restrict__ col,
                       const __half* __restrict__ src, float* __restrict__ dst) {
    int warp = (blockIdx.x * blockDim.x + threadIdx.x) >> 5;
    int lane = threadIdx.x & 31;
    int e = warp * 4;
    if (e >= N_EDGES) return;   // N_EDGES % 4 == 0

    int r0 = __ldg(row + e),     c0 = __ldg(col + e);
    int r1 = __ldg(row + e + 1), c1 = __ldg(col + e + 1);
    int r2 = __ldg(row + e + 2), c2 = __ldg(col + e + 2);
    int r3 = __ldg(row + e + 3), c3 = __ldg(col + e + 3);

    uint2 w0 = __ldg((const uint2*)(src + ((size_t)r0 << 7)) + lane);
    uint2 w1 = __ldg((const uint2*)(src + ((size_t)r1 << 7)) + lane);
    uint2 w2 = __ldg((const uint2*)(src + ((size_t)r2 << 7)) + lane);
    uint2 w3 = __ldg((const uint2*)(src + ((size_t)r3 << 7)) + lane);

    float n0 = __ldg(&g_dinv[c0]);
    float n1 = __ldg(&g_dinv[c1]);
    float n2 = __ldg(&g_dinv[c2]);
    float n3 = __ldg(&g_dinv[c3]);

    float2 f0a = __half22float2(u2h(w0.x)), f0b = __half22float2(u2h(w0.y));
    float2 f1a = __half22float2(u2h(w1.x)), f1b = __half22float2(u2h(w1.y));
    float2 f2a = __half22float2(u2h(w2.x)), f2b = __half22float2(u2h(w2.y));
    float2 f3a = __half22float2(u2h(w3.x)), f3b = __half22float2(u2h(w3.y));

    float* a0 = dst + ((size_t)c0 << 7) + lane * 4;
    float* a1 = dst + ((size_t)c1 << 7) + lane * 4;
    float* a2 = dst + ((size_t)c2 << 7) + lane * 4;
    float* a3 = dst + ((size_t)c3 << 7) + lane * 4;

    asm volatile("red.global.add.v4.f32 [%0], {%1, %2, %3, %4};"
                 :: "l"(a0), "f"(n0 * f0a.x), "f"(n0 * f0a.y),
                    "f"(n0 * f0b.x), "f"(n0 * f0b.y) : "memory");
    asm volatile("red.global.add.v4.f32 [%0], {%1, %2, %3, %4};"
                 :: "l"(a1), "f"(n1 * f1a.x), "f"(n1 * f1a.y),
                    "f"(n1 * f1b.x), "f"(n1 * f1b.y) : "memory");
    asm volatile("red.global.add.v4.f32 [%0], {%1, %2, %3, %4};"
                 :: "l"(a2), "f"(n2 * f2a.x), "f"(n2 * f2a.y),
                    "f"(n2 * f2b.x), "f"(n2 * f2b.y) : "memory");
    asm volatile("red.global.add.v4.f32 [%0], {%1, %2, %3, %4};"
                 :: "l"(a3), "f"(n3 * f3a.x), "f"(n3 * f3a.y),
                    "f"(n3 * f3b.x), "f"(n3 * f3b.y) : "memory");
}

// ---------------- relu + dropout + segment-max pool (reads agg) -------------
__global__ void k_pool(const float* __restrict__ agg, const int* __restrict__ mask,
                       const int* __restrict__ batch) {
    int t  = threadIdx.x;           // feature
    int n0 = blockIdx.x * 64;
    int cur = -1;
    float mx = 0.f;
    for (int i = 0; i < 64; i++) {
        int n = n0 + i;
        if (n >= N_NODES) break;
        int bid = batch[n];
        if (bid != cur) {
            if (cur >= 0) atomicMax((int*)&g_pool[cur * F + t], __float_as_int(mx));
            cur = bid;
            mx = 0.f;
        }
        size_t idx = (size_t)n * F + t;
        float v = fmaxf(agg[idx], 0.f);
        v *= (float)(mask[idx] << 1);   // dropout: *mask*2
        mx = fmaxf(mx, v);
    }
    if (cur >= 0) atomicMax((int*)&g_pool[cur * F + t], __float_as_int(mx));
}

// ---------------- head: relu(pool @ Wm + bm) @ Wf + bf -> out[64,32] ----------
__global__ void k_head(const float* __restrict__ Wm, const float* __restrict__ bm,
                       const float* __restrict__ Wf, const float* __restrict__ bf,
                       float* __restrict__ out) {
    __shared__ float sh[NGRAPH * F];
    int t = threadIdx.x;               // 256
    for (int i = t; i < NGRAPH * F; i += 256) {
        int g = i >> 7, f = i & 127;
        float acc = bm[f];
        const float* pg = g_pool + g * F;
        #pragma unroll 8
        for (int k = 0; k < 128; k++) acc = fmaf(pg[k], Wm[k * F + f], acc);
        sh[i] = fmaxf(acc, 0.f);
    }
    __syncthreads();
    for (int i = t; i < NGRAPH * 32; i += 256) {
        int g = i >> 5, o = i & 31;
        float acc = bf[o];
        const float* hg = sh + g * F;
        #pragma unroll 8
        for (int k = 0; k < 128; k++) acc = fmaf(hg[k], Wf[k * 32 + o], acc);
        out[i] = acc;
    }
}

// ---------------- launch ----------------
extern "C" void kernel_launch(void* const* d_in, const int* in_sizes, int n_in,
                              void* d_out, int out_size) {
    const float* x     = (const float*)d_in[0];
    const int*   ei    = (const int*)d_in[1];
    const int*   batch = (const int*)d_in[2];
    const int*   mask  = (const int*)d_in[3];
    const float* W1    = (const float*)d_in[4];
    const float* b1    = (const float*)d_in[5];
    const float* W2    = (const float*)d_in[6];
    const float* b2    = (const float*)d_in[7];
    const float* Wm    = (const float*)d_in[8];
    const float* bm    = (const float*)d_in[9];
    const float* Wf    = (const float*)d_in[10];
    const float* bf    = (const float*)d_in[11];
    float* out = (float*)d_out;
    (void)in_sizes; (void)n_in; (void)out_size;

    __half* xwh;
    float *agg, *pool;
    int* deg;
    cudaGetSymbolAddress((void**)&xwh,  g_xwh);
    cudaGetSymbolAddress((void**)&agg,  g_agg);
    cudaGetSymbolAddress((void**)&pool, g_pool);
    cudaGetSymbolAddress((void**)&deg,  g_deg);

    (void)cudaFuncSetAttribute(k_gemm_init<false>,
                               cudaFuncAttributeMaxDynamicSharedMemorySize, GEMM_SMEM);
    (void)cudaFuncSetAttribute(k_gemm_init<true>,
                               cudaFuncAttributeMaxDynamicSharedMemorySize, GEMM_SMEM);

    const int* row = ei;
    const int* col = ei + N_EDGES;

    const int gemm_blocks = 1563;                 // ceil(100000/64)
    const int pool_blocks = 1563;                 // ceil(100000/64)
    const int edge_blocks = 50000;                // 1 warp = 4 edges, 8 warps/blk

    // ---- setup ----
    k_zero_i<<<391, 256>>>(deg, N_NODES);
    k_zero_f4<<<8, 256>>>((float4*)pool, NGRAPH * F / 4);
    k_degree<<<1184, 256>>>(col);
    k_dinv<<<391, 256>>>();

    // ---- layer 1 ----
    k_gemm_init<false><<<gemm_blocks, 256, GEMM_SMEM>>>(x, W1, b1, xwh, agg, N_NODES);
    k_edge<<<edge_blocks, 256>>>(row, col, xwh, agg);

    // ---- layer 2 (relu of layer-1 agg fused into GEMM A load) ----
    k_gemm_init<true><<<gemm_blocks, 256, GEMM_SMEM>>>(agg, W2, b2, xwh, agg, N_NODES);
    k_edge<<<edge_blocks, 256>>>(row, col, xwh, agg);

    // ---- relu + dropout + max-pool ----
    k_pool<<<pool_blocks, 128>>>(agg, mask, batch);

    // ---- MLP head ----
    k_head<<<1, 256>>>(Wm, bm, Wf, bf, out);
}

// round 14
// speedup vs baseline: 2.5111x; 1.2594x over previous
#include <cuda_runtime.h>
#include <cuda_fp16.h>

#define N_NODES 100000
#define N_EDGES 1600000
#define F 128
#define NGRAPH 64

// ---------------- scratch (device globals; no allocations) ----------------
__device__ float  g_dinv[N_NODES];
__device__ int    g_deg[N_NODES];
__device__ __half g_xwh [(size_t)N_NODES * F];  // dinv[row] * xw  (messages)
__device__ __half g_aggh[(size_t)N_NODES * F];  // fp16 accumulator
__device__ float  g_pool[NGRAPH * F];

// ---------------- helpers ----------------
__device__ __forceinline__ unsigned h2u(__half2 h) {
    union { __half2 h; unsigned u; } cvt; cvt.h = h; return cvt.u;
}
__device__ __forceinline__ __half2 u2h(unsigned u) {
    union { unsigned u; __half2 h; } cvt; cvt.u = u; return cvt.h;
}
__device__ __forceinline__ unsigned smem_u32(const void* p) {
    return (unsigned)__cvta_generic_to_shared(p);
}

#define LDSM_X4(r0, r1, r2, r3, addr) \
    asm volatile("ldmatrix.sync.aligned.m8n8.x4.shared.b16 {%0,%1,%2,%3},[%4];" \
                 : "=r"(r0), "=r"(r1), "=r"(r2), "=r"(r3) : "r"(addr))
#define LDSM_X4_T(r0, r1, r2, r3, addr) \
    asm volatile("ldmatrix.sync.aligned.m8n8.x4.trans.shared.b16 {%0,%1,%2,%3},[%4];" \
                 : "=r"(r0), "=r"(r1), "=r"(r2), "=r"(r3) : "r"(addr))
#define MMA16816(c, a0, a1, a2, a3, b0, b1) \
    asm volatile("mma.sync.aligned.m16n8k16.row.col.f32.f16.f16.f32 " \
                 "{%0,%1,%2,%3},{%4,%5,%6,%7},{%8,%9},{%0,%1,%2,%3};" \
                 : "+f"(c[0]), "+f"(c[1]), "+f"(c[2]), "+f"(c[3]) \
                 : "r"(a0), "r"(a1), "r"(a2), "r"(a3), "r"(b0), "r"(b1))

// ---------------- small kernels ----------------
__global__ void k_zero_i(int* p, int n) {
    int i = blockIdx.x * blockDim.x + threadIdx.x;
    if (i < n) p[i] = 0;
}
__global__ void k_zero_f4(float4* p, int n4) {
    int i = blockIdx.x * blockDim.x + threadIdx.x;
    if (i < n4) p[i] = make_float4(0.f, 0.f, 0.f, 0.f);
}
__global__ void k_degree(const int* __restrict__ col) {
    int i = blockIdx.x * blockDim.x + threadIdx.x;
    int stride = gridDim.x * blockDim.x;
    for (; i < N_EDGES; i += stride) atomicAdd(&g_deg[col[i]], 1);
}
__global__ void k_dinv() {
    int i = blockIdx.x * blockDim.x + threadIdx.x;
    if (i < N_NODES) g_dinv[i] = rsqrtf((float)g_deg[i] + 2.0f);
}

// ---- A-tile loaders (fp32 input: no relu; fp16 input: relu fused) ----
__device__ __forceinline__ void load_a_tile(const float* __restrict__ A, __half* As,
                                            int t, int m0, int M) {
    for (int i = t; i < 64 * 32; i += 256) {
        int r = i >> 5, c = i & 31;
        float4 v = make_float4(0.f, 0.f, 0.f, 0.f);
        if (m0 + r < M) v = __ldg((const float4*)(A + (size_t)(m0 + r) * F) + c);
        uint2 hp;
        hp.x = h2u(__floats2half2_rn(v.x, v.y));
        hp.y = h2u(__floats2half2_rn(v.z, v.w));
        *((uint2*)(As + r * 136 + c * 4)) = hp;
    }
}
__device__ __forceinline__ void load_a_tile(const __half* __restrict__ A, __half* As,
                                            int t, int m0, int M) {
    const __half2 z = __floats2half2_rn(0.f, 0.f);
    for (int i = t; i < 64 * 32; i += 256) {
        int r = i >> 5, c = i & 31;
        uint2 v = make_uint2(0u, 0u);
        if (m0 + r < M) v = __ldg((const uint2*)(A + (size_t)(m0 + r) * F) + c);
        uint2 hp;
        hp.x = h2u(__hmax2(u2h(v.x), z));   // relu fused
        hp.y = h2u(__hmax2(u2h(v.y), z));
        *((uint2*)(As + r * 136 + c * 4)) = hp;
    }
}

// ---- Tensor-core GEMM + fused epilogue (HMMA m16n8k16, fp32 accum):
//   t    = A' @ W   (A' = relu(A) when A is fp16 layer-2 input)
//   xwh  = fp16(dinv[r] * t)
//   aggh = fp16(2*dinv^2 * t + bias)   (seed for fp16 atomic accumulation)
#define APITCH 136
#define GEMM_SMEM ((64 * APITCH + 128 * APITCH) * 2)
template<typename AT>
__global__ void k_gemm_init(const AT* __restrict__ A, const float* __restrict__ W,
                            const float* __restrict__ bias,
                            __half* __restrict__ xwh, __half* __restrict__ aggh, int M) {
    extern __shared__ __half sm[];
    __half* As = sm;                 // 64 x 136
    __half* Ws = sm + 64 * APITCH;   // 128 x 136
    const int t  = threadIdx.x;      // 256 threads
    const int m0 = blockIdx.x * 64;

    #pragma unroll 4
    for (int i = t; i < 128 * 32; i += 256) {
        int r = i >> 5, c = i & 31;
        float4 v = ((const float4*)W)[i];
        uint2 hp;
        hp.x = h2u(__floats2half2_rn(v.x, v.y));
        hp.y = h2u(__floats2half2_rn(v.z, v.w));
        *((uint2*)(Ws + r * APITCH + c * 4)) = hp;
    }
    load_a_tile(A, As, t, m0, M);
    __syncthreads();

    const int lane = t & 31;
    const int wid  = t >> 5;
    const int wm   = wid & 3;
    const int wn   = wid >> 2;

    float c[8][4];
    #pragma unroll
    for (int i = 0; i < 8; i++)
        #pragma unroll
        for (int j = 0; j < 4; j++) c[i][j] = 0.f;

    const int lr = lane & 15;
    const int lc = lane >> 4;

    #pragma unroll
    for (int k0 = 0; k0 < 8; k0++) {
        unsigned a0, a1, a2, a3;
        unsigned aaddr = smem_u32(As + (wm * 16 + lr) * APITCH + k0 * 16 + lc * 8);
        LDSM_X4(a0, a1, a2, a3, aaddr);
        #pragma unroll
        for (int tp = 0; tp < 4; tp++) {
            unsigned b0, b1, b2, b3;
            unsigned baddr = smem_u32(Ws + (k0 * 16 + lr) * APITCH
                                      + wn * 64 + tp * 16 + lc * 8);
            LDSM_X4_T(b0, b1, b2, b3, baddr);
            MMA16816(c[2 * tp],     a0, a1, a2, a3, b0, b1);
            MMA16816(c[2 * tp + 1], a0, a1, a2, a3, b2, b3);
        }
    }

    const int r1 = m0 + wm * 16 + (lane >> 2);
    const int r2 = r1 + 8;
    float d1 = 0.f, d2 = 0.f;
    if (r1 < M) d1 = g_dinv[r1];
    if (r2 < M) d2 = g_dinv[r2];
    const float s1 = 2.f * d1 * d1;
    const float s2 = 2.f * d2 * d2;

    #pragma unroll
    for (int t8 = 0; t8 < 8; t8++) {
        int nb = wn * 64 + t8 * 8 + 2 * (lane & 3);
        float2 bv = ((const float2*)bias)[nb >> 1];
        if (r1 < M) {
            *((unsigned*)(xwh + (size_t)r1 * F + nb)) =
                h2u(__floats2half2_rn(d1 * c[t8][0], d1 * c[t8][1]));
            *((unsigned*)(aggh + (size_t)r1 * F + nb)) =
                h2u(__floats2half2_rn(fmaf(s1, c[t8][0], bv.x),
                                      fmaf(s1, c[t8][1], bv.y)));
        }
        if (r2 < M) {
            *((unsigned*)(xwh + (size_t)r2 * F + nb)) =
                h2u(__floats2half2_rn(d2 * c[t8][2], d2 * c[t8][3]));
            *((unsigned*)(aggh + (size_t)r2 * F + nb)) =
                h2u(__floats2half2_rn(fmaf(s2, c[t8][2], bv.x),
                                      fmaf(s2, c[t8][3], bv.y)));
        }
    }
}

// ---------------- edge scatter: aggh[col] += dinv[col] * xwh[row] (fp16) ----
// Warp handles 8 edges: half-warp (16 lanes) per edge, lane owns a 16B chunk
// (8 fp16 features). 16 red.v4.f16x2 ops per edge = HALF the lane-ops and
// RMW bytes of the f32 version.
__global__ void k_edge(const int* __restrict__ row, const int* __restrict__ col,
                       const __half* __restrict__ src, __half* __restrict__ dst) {
    int warp = (blockIdx.x * blockDim.x + threadIdx.x) >> 5;
    int lane = threadIdx.x & 31;
    int hw   = lane >> 4;     // which edge of the pair
    int c16  = lane & 15;     // 16B chunk within the 256B row
    int e0 = warp * 8;
    if (e0 >= N_EDGES) return;   // N_EDGES % 8 == 0 -> full octet or nothing

    #pragma unroll
    for (int p = 0; p < 4; p++) {
        int e = e0 + 2 * p + hw;
        int r = __ldg(row + e);
        int cc = __ldg(col + e);
        float n = __ldg(&g_dinv[cc]);
        uint4 w = __ldg((const uint4*)(src + ((size_t)r << 7)) + c16);
        float2 fa = __half22float2(u2h(w.x));
        float2 fb = __half22float2(u2h(w.y));
        float2 fc = __half22float2(u2h(w.z));
        float2 fd = __half22float2(u2h(w.w));
        unsigned o0 = h2u(__floats2half2_rn(n * fa.x, n * fa.y));
        unsigned o1 = h2u(__floats2half2_rn(n * fb.x, n * fb.y));
        unsigned o2 = h2u(__floats2half2_rn(n * fc.x, n * fc.y));
        unsigned o3 = h2u(__floats2half2_rn(n * fd.x, n * fd.y));
        __half* addr = dst + ((size_t)cc << 7) + c16 * 8;
        asm volatile("red.global.add.noftz.v4.f16x2 [%0], {%1,%2,%3,%4};"
                     :: "l"(addr), "r"(o0), "r"(o1), "r"(o2), "r"(o3) : "memory");
    }
}

// ---------------- relu + dropout + segment-max pool (reads fp16 aggh) -------
__global__ void k_pool(const __half* __restrict__ aggh, const int* __restrict__ mask,
                       const int* __restrict__ batch) {
    int t  = threadIdx.x;           // feature
    int n0 = blockIdx.x * 64;
    int cur = -1;
    float mx = 0.f;
    for (int i = 0; i < 64; i++) {
        int n = n0 + i;
        if (n >= N_NODES) break;
        int bid = batch[n];
        if (bid != cur) {
            if (cur >= 0) atomicMax((int*)&g_pool[cur * F + t], __float_as_int(mx));
            cur = bid;
            mx = 0.f;
        }
        size_t idx = (size_t)n * F + t;
        float v = fmaxf(__half2float(aggh[idx]), 0.f);
        v *= (float)(mask[idx] << 1);   // dropout: *mask*2
        mx = fmaxf(mx, v);
    }
    if (cur >= 0) atomicMax((int*)&g_pool[cur * F + t], __float_as_int(mx));
}

// ---------------- head: relu(pool @ Wm + bm) @ Wf + bf -> out[64,32] ----------
__global__ void k_head(const float* __restrict__ Wm, const float* __restrict__ bm,
                       const float* __restrict__ Wf, const float* __restrict__ bf,
                       float* __restrict__ out) {
    __shared__ float sh[NGRAPH * F];
    int t = threadIdx.x;               // 256
    for (int i = t; i < NGRAPH * F; i += 256) {
        int g = i >> 7, f = i & 127;
        float acc = bm[f];
        const float* pg = g_pool + g * F;
        #pragma unroll 8
        for (int k = 0; k < 128; k++) acc = fmaf(pg[k], Wm[k * F + f], acc);
        sh[i] = fmaxf(acc, 0.f);
    }
    __syncthreads();
    for (int i = t; i < NGRAPH * 32; i += 256) {
        int g = i >> 5, o = i & 31;
        float acc = bf[o];
        const float* hg = sh + g * F;
        #pragma unroll 8
        for (int k = 0; k < 128; k++) acc = fmaf(hg[k], Wf[k * 32 + o], acc);
        out[i] = acc;
    }
}

// ---------------- launch ----------------
extern "C" void kernel_launch(void* const* d_in, const int* in_sizes, int n_in,
                              void* d_out, int out_size) {
    const float* x     = (const float*)d_in[0];
    const int*   ei    = (const int*)d_in[1];
    const int*   batch = (const int*)d_in[2];
    const int*   mask  = (const int*)d_in[3];
    const float* W1    = (const float*)d_in[4];
    const float* b1    = (const float*)d_in[5];
    const float* W2    = (const float*)d_in[6];
    const float* b2    = (const float*)d_in[7];
    const float* Wm    = (const float*)d_in[8];
    const float* bm    = (const float*)d_in[9];
    const float* Wf    = (const float*)d_in[10];
    const float* bf    = (const float*)d_in[11];
    float* out = (float*)d_out;
    (void)in_sizes; (void)n_in; (void)out_size;

    __half *xwh, *aggh;
    float* pool;
    int* deg;
    cudaGetSymbolAddress((void**)&xwh,  g_xwh);
    cudaGetSymbolAddress((void**)&aggh, g_aggh);
    cudaGetSymbolAddress((void**)&pool, g_pool);
    cudaGetSymbolAddress((void**)&deg,  g_deg);

    (void)cudaFuncSetAttribute(k_gemm_init<float>,
                               cudaFuncAttributeMaxDynamicSharedMemorySize, GEMM_SMEM);
    (void)cudaFuncSetAttribute(k_gemm_init<__half>,
                               cudaFuncAttributeMaxDynamicSharedMemorySize, GEMM_SMEM);

    const int* row = ei;
    const int* col = ei + N_EDGES;

    const int gemm_blocks = 1563;                 // ceil(100000/64)
    const int pool_blocks = 1563;                 // ceil(100000/64)
    const int edge_blocks = 25000;                // 1 warp = 8 edges, 8 warps/blk

    // ---- setup ----
    k_zero_i<<<391, 256>>>(deg, N_NODES);
    k_zero_f4<<<8, 256>>>((float4*)pool, NGRAPH * F / 4);
    k_degree<<<1184, 256>>>(col);
    k_dinv<<<391, 256>>>();

    // ---- layer 1 ----
    k_gemm_init<float><<<gemm_blocks, 256, GEMM_SMEM>>>(x, W1, b1, xwh, aggh, N_NODES);
    k_edge<<<edge_blocks, 256>>>(row, col, xwh, aggh);

    // ---- layer 2 (relu of layer-1 aggh fused into fp16 GEMM A load) ----
    k_gemm_init<__half><<<gemm_blocks, 256, GEMM_SMEM>>>(aggh, W2, b2, xwh, aggh, N_NODES);
    k_edge<<<edge_blocks, 256>>>(row, col, xwh, aggh);

    // ---- relu + dropout + max-pool ----
    k_pool<<<pool_blocks, 128>>>(aggh, mask, batch);

    // ---- MLP head ----
    k_head<<<1, 256>>>(Wm, bm, Wf, bf, out);
}

// round 16
// speedup vs baseline: 2.5474x; 1.0144x over previous
#include <cuda_runtime.h>
#include <cuda_fp16.h>

#define N_NODES 100000
#define N_EDGES 1600000
#define F 128
#define NGRAPH 64

// ---------------- scratch (device globals; no allocations) ----------------
__device__ float  g_dinv[N_NODES];
__device__ int    g_deg[N_NODES];
__device__ __half g_xwh [(size_t)N_NODES * F];  // dinv[row] * xw  (messages)
__device__ __half g_aggh[(size_t)N_NODES * F];  // fp16 accumulator
__device__ float  g_pool[NGRAPH * F];

// ---------------- helpers ----------------
__device__ __forceinline__ unsigned h2u(__half2 h) {
    union { __half2 h; unsigned u; } cvt; cvt.h = h; return cvt.u;
}
__device__ __forceinline__ __half2 u2h(unsigned u) {
    union { unsigned u; __half2 h; } cvt; cvt.u = u; return cvt.h;
}
__device__ __forceinline__ unsigned smem_u32(const void* p) {
    return (unsigned)__cvta_generic_to_shared(p);
}

#define LDSM_X4(r0, r1, r2, r3, addr) \
    asm volatile("ldmatrix.sync.aligned.m8n8.x4.shared.b16 {%0,%1,%2,%3},[%4];" \
                 : "=r"(r0), "=r"(r1), "=r"(r2), "=r"(r3) : "r"(addr))
#define LDSM_X4_T(r0, r1, r2, r3, addr) \
    asm volatile("ldmatrix.sync.aligned.m8n8.x4.trans.shared.b16 {%0,%1,%2,%3},[%4];" \
                 : "=r"(r0), "=r"(r1), "=r"(r2), "=r"(r3) : "r"(addr))
#define MMA16816(c, a0, a1, a2, a3, b0, b1) \
    asm volatile("mma.sync.aligned.m16n8k16.row.col.f32.f16.f16.f32 " \
                 "{%0,%1,%2,%3},{%4,%5,%6,%7},{%8,%9},{%0,%1,%2,%3};" \
                 : "+f"(c[0]), "+f"(c[1]), "+f"(c[2]), "+f"(c[3]) \
                 : "r"(a0), "r"(a1), "r"(a2), "r"(a3), "r"(b0), "r"(b1))

// ---------------- small kernels ----------------
__global__ void k_zero_i(int* p, int n) {
    int i = blockIdx.x * blockDim.x + threadIdx.x;
    if (i < n) p[i] = 0;
}
__global__ void k_zero_f4(float4* p, int n4) {
    int i = blockIdx.x * blockDim.x + threadIdx.x;
    if (i < n4) p[i] = make_float4(0.f, 0.f, 0.f, 0.f);
}
__global__ void k_degree(const int* __restrict__ col) {
    int i = blockIdx.x * blockDim.x + threadIdx.x;
    int stride = gridDim.x * blockDim.x;
    for (; i < N_EDGES; i += stride) atomicAdd(&g_deg[col[i]], 1);
}
__global__ void k_dinv() {
    int i = blockIdx.x * blockDim.x + threadIdx.x;
    if (i < N_NODES) g_dinv[i] = rsqrtf((float)g_deg[i] + 2.0f);
}

// ---- A-tile loaders (fp32 input: no relu; fp16 input: relu fused) ----
__device__ __forceinline__ void load_a_tile(const float* __restrict__ A, __half* As,
                                            int t, int m0, int M) {
    for (int i = t; i < 64 * 32; i += 256) {
        int r = i >> 5, c = i & 31;
        float4 v = make_float4(0.f, 0.f, 0.f, 0.f);
        if (m0 + r < M) v = __ldg((const float4*)(A + (size_t)(m0 + r) * F) + c);
        uint2 hp;
        hp.x = h2u(__floats2half2_rn(v.x, v.y));
        hp.y = h2u(__floats2half2_rn(v.z, v.w));
        *((uint2*)(As + r * 136 + c * 4)) = hp;
    }
}
__device__ __forceinline__ void load_a_tile(const __half* __restrict__ A, __half* As,
                                            int t, int m0, int M) {
    const __half2 z = __floats2half2_rn(0.f, 0.f);
    for (int i = t; i < 64 * 32; i += 256) {
        int r = i >> 5, c = i & 31;
        uint2 v = make_uint2(0u, 0u);
        if (m0 + r < M) v = __ldg((const uint2*)(A + (size_t)(m0 + r) * F) + c);
        uint2 hp;
        hp.x = h2u(__hmax2(u2h(v.x), z));   // relu fused
        hp.y = h2u(__hmax2(u2h(v.y), z));
        *((uint2*)(As + r * 136 + c * 4)) = hp;
    }
}

// ---- Tensor-core GEMM + fused epilogue (HMMA m16n8k16, fp32 accum):
//   t    = A' @ W   (A' = relu(A) when A is fp16 layer-2 input)
//   xwh  = fp16(dinv[r] * t)
//   aggh = fp16(2*dinv^2 * t + bias)   (seed for fp16 atomic accumulation)
#define APITCH 136
#define GEMM_SMEM ((64 * APITCH + 128 * APITCH) * 2)
template<typename AT>
__global__ void k_gemm_init(const AT* __restrict__ A, const float* __restrict__ W,
                            const float* __restrict__ bias,
                            __half* __restrict__ xwh, __half* __restrict__ aggh, int M) {
    extern __shared__ __half sm[];
    __half* As = sm;                 // 64 x 136
    __half* Ws = sm + 64 * APITCH;   // 128 x 136
    const int t  = threadIdx.x;      // 256 threads
    const int m0 = blockIdx.x * 64;

    #pragma unroll 4
    for (int i = t; i < 128 * 32; i += 256) {
        int r = i >> 5, c = i & 31;
        float4 v = ((const float4*)W)[i];
        uint2 hp;
        hp.x = h2u(__floats2half2_rn(v.x, v.y));
        hp.y = h2u(__floats2half2_rn(v.z, v.w));
        *((uint2*)(Ws + r * APITCH + c * 4)) = hp;
    }
    load_a_tile(A, As, t, m0, M);
    __syncthreads();

    const int lane = t & 31;
    const int wid  = t >> 5;
    const int wm   = wid & 3;
    const int wn   = wid >> 2;

    float c[8][4];
    #pragma unroll
    for (int i = 0; i < 8; i++)
        #pragma unroll
        for (int j = 0; j < 4; j++) c[i][j] = 0.f;

    const int lr = lane & 15;
    const int lc = lane >> 4;

    #pragma unroll
    for (int k0 = 0; k0 < 8; k0++) {
        unsigned a0, a1, a2, a3;
        unsigned aaddr = smem_u32(As + (wm * 16 + lr) * APITCH + k0 * 16 + lc * 8);
        LDSM_X4(a0, a1, a2, a3, aaddr);
        #pragma unroll
        for (int tp = 0; tp < 4; tp++) {
            unsigned b0, b1, b2, b3;
            unsigned baddr = smem_u32(Ws + (k0 * 16 + lr) * APITCH
                                      + wn * 64 + tp * 16 + lc * 8);
            LDSM_X4_T(b0, b1, b2, b3, baddr);
            MMA16816(c[2 * tp],     a0, a1, a2, a3, b0, b1);
            MMA16816(c[2 * tp + 1], a0, a1, a2, a3, b2, b3);
        }
    }

    const int r1 = m0 + wm * 16 + (lane >> 2);
    const int r2 = r1 + 8;
    float d1 = 0.f, d2 = 0.f;
    if (r1 < M) d1 = g_dinv[r1];
    if (r2 < M) d2 = g_dinv[r2];
    const float s1 = 2.f * d1 * d1;
    const float s2 = 2.f * d2 * d2;

    #pragma unroll
    for (int t8 = 0; t8 < 8; t8++) {
        int nb = wn * 64 + t8 * 8 + 2 * (lane & 3);
        float2 bv = ((const float2*)bias)[nb >> 1];
        if (r1 < M) {
            *((unsigned*)(xwh + (size_t)r1 * F + nb)) =
                h2u(__floats2half2_rn(d1 * c[t8][0], d1 * c[t8][1]));
            *((unsigned*)(aggh + (size_t)r1 * F + nb)) =
                h2u(__floats2half2_rn(fmaf(s1, c[t8][0], bv.x),
                                      fmaf(s1, c[t8][1], bv.y)));
        }
        if (r2 < M) {
            *((unsigned*)(xwh + (size_t)r2 * F + nb)) =
                h2u(__floats2half2_rn(d2 * c[t8][2], d2 * c[t8][3]));
            *((unsigned*)(aggh + (size_t)r2 * F + nb)) =
                h2u(__floats2half2_rn(fmaf(s2, c[t8][2], bv.x),
                                      fmaf(s2, c[t8][3], bv.y)));
        }
    }
}

// ---------------- edge scatter: aggh[col] += dinv[col] * xwh[row] (fp16) ----
// Warp handles 8 edges: half-warp per edge, lane owns one 16B chunk (8 fp16).
// Phase-batched: all index loads, then all 4 gathers + dinv (8 loads in
// flight), then all 4 red ops — the "memory"-clobbered reds would otherwise
// serialize the gathers (compiler barrier), collapsing MLP to 1.
__global__ void k_edge(const int* __restrict__ row, const int* __restrict__ col,
                       const __half* __restrict__ src, __half* __restrict__ dst) {
    int warp = (blockIdx.x * blockDim.x + threadIdx.x) >> 5;
    int lane = threadIdx.x & 31;
    int hw   = lane >> 4;     // which edge of the pair
    int c16  = lane & 15;     // 16B chunk within the 256B row
    int e0 = warp * 8;
    if (e0 >= N_EDGES) return;   // N_EDGES % 8 == 0 -> full octet or nothing

    int r[4], cc[4];
    #pragma unroll
    for (int p = 0; p < 4; p++) {
        int e = e0 + 2 * p + hw;
        r[p]  = __ldg(row + e);
        cc[p] = __ldg(col + e);
    }

    uint4 w[4];
    float n[4];
    #pragma unroll
    for (int p = 0; p < 4; p++)
        w[p] = __ldg((const uint4*)(src + ((size_t)r[p] << 7)) + c16);
    #pragma unroll
    for (int p = 0; p < 4; p++)
        n[p] = __ldg(&g_dinv[cc[p]]);

    unsigned o[4][4];
    #pragma unroll
    for (int p = 0; p < 4; p++) {
        float2 fa = __half22float2(u2h(w[p].x));
        float2 fb = __half22float2(u2h(w[p].y));
        float2 fc = __half22float2(u2h(w[p].z));
        float2 fd = __half22float2(u2h(w[p].w));
        o[p][0] = h2u(__floats2half2_rn(n[p] * fa.x, n[p] * fa.y));
        o[p][1] = h2u(__floats2half2_rn(n[p] * fb.x, n[p] * fb.y));
        o[p][2] = h2u(__floats2half2_rn(n[p] * fc.x, n[p] * fc.y));
        o[p][3] = h2u(__floats2half2_rn(n[p] * fd.x, n[p] * fd.y));
    }

    #pragma unroll
    for (int p = 0; p < 4; p++) {
        __half* addr = dst + ((size_t)cc[p] << 7) + c16 * 8;
        asm volatile("red.global.add.noftz.v4.f16x2 [%0], {%1,%2,%3,%4};"
                     :: "l"(addr), "r"(o[p][0]), "r"(o[p][1]),
                        "r"(o[p][2]), "r"(o[p][3]) : "memory");
    }
}

// ---------------- relu + dropout + segment-max pool (reads fp16 aggh) -------
__global__ void k_pool(const __half* __restrict__ aggh, const int* __restrict__ mask,
                       const int* __restrict__ batch) {
    int t  = threadIdx.x;           // feature
    int n0 = blockIdx.x * 64;
    int cur = -1;
    float mx = 0.f;
    for (int i = 0; i < 64; i++) {
        int n = n0 + i;
        if (n >= N_NODES) break;
        int bid = batch[n];
        if (bid != cur) {
            if (cur >= 0) atomicMax((int*)&g_pool[cur * F + t], __float_as_int(mx));
            cur = bid;
            mx = 0.f;
        }
        size_t idx = (size_t)n * F + t;
        float v = fmaxf(__half2float(aggh[idx]), 0.f);
        v *= (float)(mask[idx] << 1);   // dropout: *mask*2
        mx = fmaxf(mx, v);
    }
    if (cur >= 0) atomicMax((int*)&g_pool[cur * F + t], __float_as_int(mx));
}

// ---------------- head: relu(pool @ Wm + bm) @ Wf + bf -> out[64,32] ----------
__global__ void k_head(const float* __restrict__ Wm, const float* __restrict__ bm,
                       const float* __restrict__ Wf, const float* __restrict__ bf,
                       float* __restrict__ out) {
    __shared__ float sh[NGRAPH * F];
    int t = threadIdx.x;               // 256
    for (int i = t; i < NGRAPH * F; i += 256) {
        int g = i >> 7, f = i & 127;
        float acc = bm[f];
        const float* pg = g_pool + g * F;
        #pragma unroll 8
        for (int k = 0; k < 128; k++) acc = fmaf(pg[k], Wm[k * F + f], acc);
        sh[i] = fmaxf(acc, 0.f);
    }
    __syncthreads();
    for (int i = t; i < NGRAPH * 32; i += 256) {
        int g = i >> 5, o = i & 31;
        float acc = bf[o];
        const float* hg = sh + g * F;
        #pragma unroll 8
        for (int k = 0; k < 128; k++) acc = fmaf(hg[k], Wf[k * 32 + o], acc);
        out[i] = acc;
    }
}

// ---------------- launch ----------------
extern "C" void kernel_launch(void* const* d_in, const int* in_sizes, int n_in,
                              void* d_out, int out_size) {
    const float* x     = (const float*)d_in[0];
    const int*   ei    = (const int*)d_in[1];
    const int*   batch = (const int*)d_in[2];
    const int*   mask  = (const int*)d_in[3];
    const float* W1    = (const float*)d_in[4];
    const float* b1    = (const float*)d_in[5];
    const float* W2    = (const float*)d_in[6];
    const float* b2    = (const float*)d_in[7];
    const float* Wm    = (const float*)d_in[8];
    const float* bm    = (const float*)d_in[9];
    const float* Wf    = (const float*)d_in[10];
    const float* bf    = (const float*)d_in[11];
    float* out = (float*)d_out;
    (void)in_sizes; (void)n_in; (void)out_size;

    __half *xwh, *aggh;
    float* pool;
    int* deg;
    cudaGetSymbolAddress((void**)&xwh,  g_xwh);
    cudaGetSymbolAddress((void**)&aggh, g_aggh);
    cudaGetSymbolAddress((void**)&pool, g_pool);
    cudaGetSymbolAddress((void**)&deg,  g_deg);

    (void)cudaFuncSetAttribute(k_gemm_init<float>,
                               cudaFuncAttributeMaxDynamicSharedMemorySize, GEMM_SMEM);
    (void)cudaFuncSetAttribute(k_gemm_init<__half>,
                               cudaFuncAttributeMaxDynamicSharedMemorySize, GEMM_SMEM);

    const int* row = ei;
    const int* col = ei + N_EDGES;

    const int gemm_blocks = 1563;                 // ceil(100000/64)
    const int pool_blocks = 1563;                 // ceil(100000/64)
    const int edge_blocks = 25000;                // 1 warp = 8 edges, 8 warps/blk

    // ---- setup ----
    k_zero_i<<<391, 256>>>(deg, N_NODES);
    k_zero_f4<<<8, 256>>>((float4*)pool, NGRAPH * F / 4);
    k_degree<<<1184, 256>>>(col);
    k_dinv<<<391, 256>>>();

    // ---- layer 1 ----
    k_gemm_init<float><<<gemm_blocks, 256, GEMM_SMEM>>>(x, W1, b1, xwh, aggh, N_NODES);
    k_edge<<<edge_blocks, 256>>>(row, col, xwh, aggh);

    // ---- layer 2 (relu of layer-1 aggh fused into fp16 GEMM A load) ----
    k_gemm_init<__half><<<gemm_blocks, 256, GEMM_SMEM>>>(aggh, W2, b2, xwh, aggh, N_NODES);
    k_edge<<<edge_blocks, 256>>>(row, col, xwh, aggh);

    // ---- relu + dropout + max-pool ----
    k_pool<<<pool_blocks, 128>>>(aggh, mask, batch);

    // ---- MLP head ----
    k_head<<<1, 256>>>(Wm, bm, Wf, bf, out);
}